// round 3
// baseline (speedup 1.0000x reference)
#include <cuda_runtime.h>
#include <math.h>

// GAT layer: out[v] = sum_{e: dst=v} h_v[src_e] * softmax_v(logit_e)
// logit_e = (<ft_s*ft_d*h_d, W_pi>) * sigmoid(<ft_s*ft_d, W_M[:128]> + <h_d, W_M[128:]>)
//
// Softmax shift-invariance lets us skip the segment_max pass entirely
// (logits are O(1..10), exp() safe in fp32), and the per-dst division
// distributes over the sum, so the whole layer is:
//   K0: zero out + segsum
//   K1: one pass over edges: logit -> ex=exp(logit); segsum[d]+=ex (atomic);
//       out[d] += ft_s*ex (red.global.add.v4.f32, no-return reduction)
//   K2: out[v] /= segsum[v]  (guard empty nodes -> 0)

#define NODES_MAX 50000

__device__ float g_segsum[NODES_MAX];

__global__ void gat_zero_kernel(float* __restrict__ out, int out_n, int n_nodes) {
    int i = blockIdx.x * blockDim.x + threadIdx.x;
    int stride = gridDim.x * blockDim.x;
    for (int j = i; j < out_n; j += stride) out[j] = 0.0f;
    for (int j = i; j < n_nodes; j += stride) g_segsum[j] = 0.0f;
}

__global__ __launch_bounds__(256) void gat_edge_kernel(
    const float4* __restrict__ hv,   // [N, 32] float4
    const float4* __restrict__ hd,   // [E, 32] float4
    const float4* __restrict__ Wpi4, // [32] float4
    const float4* __restrict__ WM4,  // [64] float4
    const int* __restrict__ src,
    const int* __restrict__ dst,
    float* __restrict__ out,         // [N, 128]
    int E)
{
    int e    = (int)((blockIdx.x * blockDim.x + threadIdx.x) >> 5);
    int lane = threadIdx.x & 31;
    if (e >= E) return;

    int s = __ldg(&src[e]);
    int d = __ldg(&dst[e]);

    float4 fs  = __ldg(&hv[(size_t)s * 32 + lane]);
    float4 fd  = __ldg(&hv[(size_t)d * 32 + lane]);
    float4 hde = __ldg(&hd[(size_t)e * 32 + lane]);
    float4 wpi = __ldg(&Wpi4[lane]);
    float4 wm1 = __ldg(&WM4[lane]);
    float4 wm2 = __ldg(&WM4[lane + 32]);

    float4 p;
    p.x = fs.x * fd.x; p.y = fs.y * fd.y; p.z = fs.z * fd.z; p.w = fs.w * fd.w;

    // s1 = <prod * h_d, W_pi>,  s2 = <prod, WM1> + <h_d, WM2>
    float s1 = p.x * hde.x * wpi.x + p.y * hde.y * wpi.y
             + p.z * hde.z * wpi.z + p.w * hde.w * wpi.w;
    float s2 = p.x * wm1.x + p.y * wm1.y + p.z * wm1.z + p.w * wm1.w
             + hde.x * wm2.x + hde.y * wm2.y + hde.z * wm2.z + hde.w * wm2.w;

    #pragma unroll
    for (int o = 16; o > 0; o >>= 1) {
        s1 += __shfl_xor_sync(0xFFFFFFFFu, s1, o);
        s2 += __shfl_xor_sync(0xFFFFFFFFu, s2, o);
    }

    float mask  = 1.0f / (1.0f + __expf(-s2));
    float logit = s1 * mask;
    float ex    = __expf(logit);

    if (lane == 0) atomicAdd(&g_segsum[d], ex);

    float4 m;
    m.x = fs.x * ex; m.y = fs.y * ex; m.z = fs.z * ex; m.w = fs.w * ex;

    float* op = out + (size_t)d * 128 + lane * 4;   // 16B aligned
    asm volatile("red.global.add.v4.f32 [%0], {%1, %2, %3, %4};"
                 :: "l"(op), "f"(m.x), "f"(m.y), "f"(m.z), "f"(m.w)
                 : "memory");
}

__global__ void gat_norm_kernel(float4* __restrict__ out, int n_nodes) {
    int i = blockIdx.x * blockDim.x + threadIdx.x;
    if (i >= n_nodes * 32) return;
    float s   = g_segsum[i >> 5];
    float inv = (s > 0.0f) ? (1.0f / s) : 0.0f;
    float4 v = out[i];
    v.x *= inv; v.y *= inv; v.z *= inv; v.w *= inv;
    out[i] = v;
}

extern "C" void kernel_launch(void* const* d_in, const int* in_sizes, int n_in,
                              void* d_out, int out_size) {
    const float* h_v  = (const float*)d_in[0];
    const float* h_d  = (const float*)d_in[1];
    const float* W_pi = (const float*)d_in[2];
    const float* W_M  = (const float*)d_in[3];
    const int*   src  = (const int*)d_in[4];
    const int*   dst  = (const int*)d_in[5];
    float* out = (float*)d_out;

    int n_nodes = in_sizes[0] / 128;
    int E       = in_sizes[4];

    gat_zero_kernel<<<2048, 256>>>(out, out_size, n_nodes);

    int warps_per_block = 256 / 32;                 // 8 edges per block
    int blocks = (E + warps_per_block - 1) / warps_per_block;
    gat_edge_kernel<<<blocks, 256>>>(
        (const float4*)h_v, (const float4*)h_d,
        (const float4*)W_pi, (const float4*)W_M,
        src, dst, out, E);

    int nthr = n_nodes * 32;
    gat_norm_kernel<<<(nthr + 255) / 256, 256>>>((float4*)out, n_nodes);
}

// round 4
// speedup vs baseline: 1.0141x; 1.0141x over previous
#include <cuda_runtime.h>
#include <math.h>

// GAT layer: out[v] = sum_{e: dst=v} h_v[src_e] * softmax_v(logit_e)
// logit_e = (<ft_s*ft_d*h_d, W_pi>) * sigmoid(<ft_s*ft_d, W_M[:128]> + <h_d, W_M[128:]>)
//
// Softmax shift-invariance lets us skip the segment_max pass entirely
// (logits are O(1..10), exp() safe in fp32), and the per-dst division
// distributes over the sum, so the whole layer is:
//   K0: zero out + segsum
//   K1: one pass over edges: logit -> ex=exp(logit); segsum[d]+=ex (atomic);
//       out[d] += ft_s*ex (red.global.add.v4.f32, no-return reduction)
//   K2: out[v] /= segsum[v]  (guard empty nodes -> 0)

#define NODES_MAX 50000

__device__ float g_segsum[NODES_MAX];

__global__ void gat_zero_kernel(float* __restrict__ out, int out_n, int n_nodes) {
    int i = blockIdx.x * blockDim.x + threadIdx.x;
    int stride = gridDim.x * blockDim.x;
    for (int j = i; j < out_n; j += stride) out[j] = 0.0f;
    for (int j = i; j < n_nodes; j += stride) g_segsum[j] = 0.0f;
}

__global__ __launch_bounds__(256) void gat_edge_kernel(
    const float4* __restrict__ hv,   // [N, 32] float4
    const float4* __restrict__ hd,   // [E, 32] float4
    const float4* __restrict__ Wpi4, // [32] float4
    const float4* __restrict__ WM4,  // [64] float4
    const int* __restrict__ src,
    const int* __restrict__ dst,
    float* __restrict__ out,         // [N, 128]
    int E)
{
    int e    = (int)((blockIdx.x * blockDim.x + threadIdx.x) >> 5);
    int lane = threadIdx.x & 31;
    if (e >= E) return;

    int s = __ldg(&src[e]);
    int d = __ldg(&dst[e]);

    float4 fs  = __ldg(&hv[(size_t)s * 32 + lane]);
    float4 fd  = __ldg(&hv[(size_t)d * 32 + lane]);
    float4 hde = __ldg(&hd[(size_t)e * 32 + lane]);
    float4 wpi = __ldg(&Wpi4[lane]);
    float4 wm1 = __ldg(&WM4[lane]);
    float4 wm2 = __ldg(&WM4[lane + 32]);

    float4 p;
    p.x = fs.x * fd.x; p.y = fs.y * fd.y; p.z = fs.z * fd.z; p.w = fs.w * fd.w;

    // s1 = <prod * h_d, W_pi>,  s2 = <prod, WM1> + <h_d, WM2>
    float s1 = p.x * hde.x * wpi.x + p.y * hde.y * wpi.y
             + p.z * hde.z * wpi.z + p.w * hde.w * wpi.w;
    float s2 = p.x * wm1.x + p.y * wm1.y + p.z * wm1.z + p.w * wm1.w
             + hde.x * wm2.x + hde.y * wm2.y + hde.z * wm2.z + hde.w * wm2.w;

    #pragma unroll
    for (int o = 16; o > 0; o >>= 1) {
        s1 += __shfl_xor_sync(0xFFFFFFFFu, s1, o);
        s2 += __shfl_xor_sync(0xFFFFFFFFu, s2, o);
    }

    float mask  = 1.0f / (1.0f + __expf(-s2));
    float logit = s1 * mask;
    float ex    = __expf(logit);

    if (lane == 0) atomicAdd(&g_segsum[d], ex);

    float4 m;
    m.x = fs.x * ex; m.y = fs.y * ex; m.z = fs.z * ex; m.w = fs.w * ex;

    float* op = out + (size_t)d * 128 + lane * 4;   // 16B aligned
    asm volatile("red.global.add.v4.f32 [%0], {%1, %2, %3, %4};"
                 :: "l"(op), "f"(m.x), "f"(m.y), "f"(m.z), "f"(m.w)
                 : "memory");
}

__global__ void gat_norm_kernel(float4* __restrict__ out, int n_nodes) {
    int i = blockIdx.x * blockDim.x + threadIdx.x;
    if (i >= n_nodes * 32) return;
    float s   = g_segsum[i >> 5];
    float inv = (s > 0.0f) ? (1.0f / s) : 0.0f;
    float4 v = out[i];
    v.x *= inv; v.y *= inv; v.z *= inv; v.w *= inv;
    out[i] = v;
}

extern "C" void kernel_launch(void* const* d_in, const int* in_sizes, int n_in,
                              void* d_out, int out_size) {
    const float* h_v  = (const float*)d_in[0];
    const float* h_d  = (const float*)d_in[1];
    const float* W_pi = (const float*)d_in[2];
    const float* W_M  = (const float*)d_in[3];
    const int*   src  = (const int*)d_in[4];
    const int*   dst  = (const int*)d_in[5];
    float* out = (float*)d_out;

    int n_nodes = in_sizes[0] / 128;
    int E       = in_sizes[4];

    gat_zero_kernel<<<2048, 256>>>(out, out_size, n_nodes);

    int warps_per_block = 256 / 32;                 // 8 edges per block
    int blocks = (E + warps_per_block - 1) / warps_per_block;
    gat_edge_kernel<<<blocks, 256>>>(
        (const float4*)h_v, (const float4*)h_d,
        (const float4*)W_pi, (const float4*)W_M,
        src, dst, out, E);

    int nthr = n_nodes * 32;
    gat_norm_kernel<<<(nthr + 255) / 256, 256>>>((float4*)out, n_nodes);
}